// round 9
// baseline (speedup 1.0000x reference)
#include <cuda_runtime.h>

// MetaSR collapsed to a sub-pixel 3x3 conv (see R2 analysis):
//   rel = (j&1)*0.5 exactly, r_rev = 0.5 exactly -> MLP input has 4 values
//   (one per 2x2 phase) -> pw collapses to 4 tables of (576,3).
// pred[b,(2y+dy)*128+2x+dx,o] = sum_{c,ky,kx} feat[b,c,y+ky-1,x+kx-1]
//                                  * pw[dy*2+dx][(c*9+ky*3+kx)*3+o]
//
// R7->R8: k_main reshaped px=4 -> px=2 per thread: 2048 -> 4096 warps
// (28/SM, single wave via launch_bounds(128,7)); regs ~124 -> ~70.
// Same broadcast pw reads (2 quads/warp share weights), packed f32x2 FMAs.

#define NB 4
#define NQ 16384
#define NOUT 1728
#define NTAP 576
#define PH 66   // padded H/W

// pw layout: idx = ((cc*9 + tap)*16 + cg)*12 + pat*3 + o   (c = cg*4+cc)
// Lane stride over cg = 12 words -> octet of lanes covers all 32 banks:
// conflict-free; lanes 16-31 broadcast with 0-15 -> 2 wavefronts/LDS.128.
__device__ __align__(16) float g_pw[NTAP * 12];                 // 27648 B
__device__ __align__(16) float g_featP[NB * PH * PH * 64];      // padded, ch-last

// ---------------------------------------------------------------------------
// f32x2 packed helpers (PTX-only path; ptxas won't auto-fuse)
// ---------------------------------------------------------------------------
__device__ __forceinline__ unsigned long long pk2(float a, float b) {
    unsigned long long r;
    asm("mov.b64 %0, {%1, %2};" : "=l"(r) : "f"(a), "f"(b));
    return r;
}
__device__ __forceinline__ void upk2(unsigned long long v, float& a, float& b) {
    asm("mov.b64 {%0, %1}, %2;" : "=f"(a), "=f"(b) : "l"(v));
}
__device__ __forceinline__ void ffma2(unsigned long long& d,
                                      unsigned long long a, unsigned long long b) {
    asm("fma.rn.f32x2 %0, %1, %2, %0;" : "+l"(d) : "l"(a), "l"(b));
}

// ---------------------------------------------------------------------------
// Prep kernel: 547 blocks x 256 threads, role-split.
//   blocks [0,512):   transpose feat -> g_featP interior (b,y,c-half per block)
//   blocks [512,539): pw tables (27 blocks)
//   blocks [539,547): zero the padded halo
// ---------------------------------------------------------------------------
__global__ __launch_bounds__(256) void k_prep(const float* __restrict__ feat,
                                              const float* __restrict__ w1,
                                              const float* __restrict__ b1,
                                              const float* __restrict__ w2,
                                              const float* __restrict__ b2) {
    __shared__ float sm[2080];
    int bi = blockIdx.x;
    int t = threadIdx.x;

    if (bi < 512) {
        // ---- transpose: block = (b, y, c-half). tile[32][65] in sm.
        float(*tile)[65] = reinterpret_cast<float(*)[65]>(sm);
        int b = bi >> 7;
        int y = (bi >> 1) & 63;
        int ch = (bi & 1) * 32;
        int xi = t & 63;
        int ci = t >> 6;           // 0..3
#pragma unroll
        for (int pass = 0; pass < 8; ++pass) {
            int cl = pass * 4 + ci;
            tile[cl][xi] = feat[((b * 64 + ch + cl) * 64 + y) * 64 + xi];
        }
        __syncthreads();
        int cl = t & 31;
        int xj = t >> 5;           // 0..7
#pragma unroll
        for (int pass = 0; pass < 8; ++pass) {
            int x = pass * 8 + xj;
            g_featP[((b * PH + y + 1) * PH + x + 1) * 64 + ch + cl] = tile[cl][x];
        }
    } else if (bi < 539) {
        // ---- pw tables
        float* hdd = sm;            // [4][256]
        float* part = sm + 1024;    // [4][4][64]
        {
            float a0 = w1[t];
            float a1 = w1[256 + t];
            float a2 = w1[512 + t];
            float bb = b1[t];
#pragma unroll
            for (int pat = 0; pat < 4; ++pat) {
                float ry = (pat >> 1) ? 0.5f : 0.0f;
                float rx = (pat & 1) ? 0.5f : 0.0f;
                float v = ry * a0 + rx * a1 + 0.5f * a2 + bb;
                hdd[pat * 256 + t] = v > 0.0f ? v : 0.0f;
            }
        }
        __syncthreads();
        int jt = t & 63;
        int hc = t >> 6;
        int j = (bi - 512) * 64 + jt;
        int hb = hc * 64;
        float a0 = 0.f, a1 = 0.f, a2 = 0.f, a3 = 0.f;
        const float* w2p = w2 + hb * NOUT + j;
#pragma unroll 8
        for (int hh = 0; hh < 64; ++hh) {
            float wv = w2p[hh * NOUT];
            a0 += hdd[0 * 256 + hb + hh] * wv;
            a1 += hdd[1 * 256 + hb + hh] * wv;
            a2 += hdd[2 * 256 + hb + hh] * wv;
            a3 += hdd[3 * 256 + hb + hh] * wv;
        }
        part[(hc * 4 + 0) * 64 + jt] = a0;
        part[(hc * 4 + 1) * 64 + jt] = a1;
        part[(hc * 4 + 2) * 64 + jt] = a2;
        part[(hc * 4 + 3) * 64 + jt] = a3;
        __syncthreads();
        if (hc == 0) {
            float bias = b2[j];
            int k = j / 3;
            int o = j - k * 3;
            int c = k / 9;
            int tap = k - c * 9;
            int cgi = c >> 2;
            int cci = c & 3;
            int base = ((cci * 9 + tap) * 16 + cgi) * 12 + o;
#pragma unroll
            for (int pat = 0; pat < 4; ++pat) {
                float s = part[(0 * 4 + pat) * 64 + jt] + part[(1 * 4 + pat) * 64 + jt] +
                          part[(2 * 4 + pat) * 64 + jt] + part[(3 * 4 + pat) * 64 + jt] + bias;
                g_pw[base + pat * 3] = s;
            }
        }
    } else {
        // ---- halo zero
        int hb = bi - 539;
        int b = hb >> 1;
        int halfsel = hb & 1;
        for (int idx = t; idx < 130 * 64; idx += 256) {
            int p = halfsel * 130 + (idx >> 6);
            int c = idx & 63;
            int y, x;
            if (p < 66) { y = 0; x = p; }
            else if (p < 132) { y = 65; x = p - 66; }
            else if (p < 196) { x = 0; y = p - 131; }
            else { x = 65; y = p - 195; }
            g_featP[((b * PH + y) * PH + x) * 64 + c] = 0.0f;
        }
    }
}

// ---------------------------------------------------------------------------
// Main conv kernel: 1024 blocks x 128 threads, single wave at 7 blocks/SM.
// Warp = 2 "duos" (2 x-adjacent LR px each); lane: cg = lane&15 (4-ch group),
// sub = lane>>4 (duo select). Thread: 4 ch x 9 taps x 2 px x 12 out
// (432 packed f32x2 FMAs). 3-stage reduce-scatter + 1 butterfly; direct STG.
// ---------------------------------------------------------------------------
__global__ __launch_bounds__(128, 7) void k_main(float* __restrict__ out) {
    __shared__ __align__(16) float pw_sm[NTAP * 12];
    int t = threadIdx.x;
    {
        const float4* g4 = reinterpret_cast<const float4*>(g_pw);
        float4* s4 = reinterpret_cast<float4*>(pw_sm);
#pragma unroll
        for (int i = 0; i < 14; ++i) {
            int idx = t + i * 128;
            if (idx < 1728) s4[idx] = g4[idx];
        }
    }
    __syncthreads();

    int lane = t & 31;
    int warp = t >> 5;
    int cg = lane & 15;
    int sub = lane >> 4;
    int duo = (blockIdx.x * 4 + warp) * 2 + sub;   // 0..8191
    int b = duo >> 11;
    int rem = duo & 2047;
    int y = rem >> 5;
    int x0 = (rem & 31) << 1;                       // LR x of first pixel

    unsigned long long acc[2][6];
#pragma unroll
    for (int px = 0; px < 2; ++px)
#pragma unroll
        for (int p = 0; p < 6; ++p) acc[px][p] = 0ull;

    int cb4 = cg * 4;

#pragma unroll
    for (int ky = 0; ky < 3; ++ky) {
        // padded rows y..y+2, padded cols x0..x0+3 -> unconditional loads
        const float* rp = g_featP + ((b * PH + y + ky) * PH + x0) * 64 + cb4;
        float fr[4][4];
#pragma unroll
        for (int i = 0; i < 4; ++i) {
            float4 v = *reinterpret_cast<const float4*>(rp + i * 64);
            fr[i][0] = v.x; fr[i][1] = v.y; fr[i][2] = v.z; fr[i][3] = v.w;
        }
#pragma unroll
        for (int kx = 0; kx < 3; ++kx) {
#pragma unroll
            for (int cc = 0; cc < 4; ++cc) {
                const ulonglong2* wp = reinterpret_cast<const ulonglong2*>(
                    pw_sm + ((cc * 9 + ky * 3 + kx) * 16 + cg) * 12);
                ulonglong2 wa = wp[0];
                ulonglong2 wb = wp[1];
                ulonglong2 wc = wp[2];
#pragma unroll
                for (int px = 0; px < 2; ++px) {
                    float fv = fr[kx + px][cc];
                    unsigned long long fv2 = pk2(fv, fv);
                    ffma2(acc[px][0], fv2, wa.x);
                    ffma2(acc[px][1], fv2, wa.y);
                    ffma2(acc[px][2], fv2, wb.x);
                    ffma2(acc[px][3], fv2, wb.y);
                    ffma2(acc[px][4], fv2, wc.x);
                    ffma2(acc[px][5], fv2, wc.y);
                }
            }
        }
    }

    // Unpack to 24 scalars: v[j], j = px*12 + (dy*6 + dx*3 + o)
    float v[24];
#pragma unroll
    for (int px = 0; px < 2; ++px)
#pragma unroll
        for (int p = 0; p < 6; ++p) {
            float a, bb;
            upk2(acc[px][p], a, bb);
            v[px * 12 + 2 * p] = a;
            v[px * 12 + 2 * p + 1] = bb;
        }

    // Reduce-scatter over cg bits {1,2,4}: 24 -> 12 -> 6 -> 3 values.
#pragma unroll
    for (int m = 1, n = 24; m < 8; m <<= 1, n >>= 1) {
        int half = n >> 1;
        bool hi = (cg & m) != 0;
#pragma unroll
        for (int i = 0; i < 24; ++i) {
            if (i >= half) break;
            float send = hi ? v[i] : v[i + half];
            float r = __shfl_xor_sync(0xffffffffu, send, m);
            v[i] = (hi ? v[i + half] : v[i]) + r;
        }
    }
    // Final reduction over cg bit 3 (plain butterfly add on the 3 survivors).
#pragma unroll
    for (int i = 0; i < 3; ++i)
        v[i] += __shfl_xor_sync(0xffffffffu, v[i], 8);

    // Lane (cg<8) owns j = base..base+2, base = 12*b0 + 6*b1 + 3*b2.
    if (cg < 8) {
        int base = 12 * (cg & 1) + 6 * ((cg >> 1) & 1) + 3 * ((cg >> 2) & 1);
        int px = base >= 12;
        int r12 = base - px * 12;
        int dy = r12 >= 6;
        int r6 = r12 - dy * 6;
        int dx = r6 >= 3;

        int hrq = (2 * y + dy) * 128 + 2 * (x0 + px) + dx;
        float* op = out + (b * NQ + hrq) * 3;
        op[0] = v[0];
        op[1] = v[1];
        op[2] = v[2];
    }
}

// ---------------------------------------------------------------------------
// Inputs (metadata order): feat, coord, cell, w1, b1, w2, b2.
// coord/cell are fully determined grids (collapsed analytically).
// ---------------------------------------------------------------------------
extern "C" void kernel_launch(void* const* d_in, const int* in_sizes, int n_in,
                              void* d_out, int out_size) {
    const float* feat = (const float*)d_in[0];
    const float* w1   = (const float*)d_in[3];
    const float* b1   = (const float*)d_in[4];
    const float* w2   = (const float*)d_in[5];
    const float* b2   = (const float*)d_in[6];
    float* out = (float*)d_out;

    k_prep<<<547, 256>>>(feat, w1, b1, w2, b2);
    k_main<<<1024, 128>>>(out);
}